// round 14
// baseline (speedup 1.0000x reference)
#include <cuda_runtime.h>
#include <cuda_fp16.h>
#include <math.h>
#include <stdint.h>

#define BATCH 64
#define SEQ 512
#define INPUT_DIM 512
#define HIDDEN 128
#define G3 384            // 3*HIDDEN
#define NUM_LAYERS 5
#define OUTPUT_DIM 96

typedef unsigned long long ull;

// ---------------- scratch (no allocs allowed) ----------------
__device__ float g_gx[BATCH * SEQ * G3];                       // layer-0 input gates
__device__ unsigned short g_y2h[2][BATCH][SEQ][256];           // hi[128]|lo[128] fp16 transport (ping-pong)
__device__ float g_hfinal[BATCH][HIDDEN];                      // last layer, last timestep

// ---------------- helpers ----------------
__device__ __forceinline__ ull pk2(float a, float b) {
    ull r; asm("mov.b64 %0, {%1, %2};" : "=l"(r) : "f"(a), "f"(b)); return r;
}
__device__ __forceinline__ void upk2(ull v, float& a, float& b) {
    asm("mov.b64 {%0, %1}, %2;" : "=f"(a), "=f"(b) : "l"(v));
}
__device__ __forceinline__ ull ffma2(ull a, ull b, ull c) {
    ull d; asm("fma.rn.f32x2 %0, %1, %2, %3;" : "=l"(d) : "l"(a), "l"(b), "l"(c)); return d;
}
__device__ __forceinline__ float sigm_fast(float x) {
    float e = __expf(-x);
    return __fdividef(1.0f, 1.0f + e);
}
__device__ __forceinline__ float tanh_fast(float x) {
    float e = __expf(-2.0f * x);
    return 1.0f - __fdividef(2.0f * e, 1.0f + e);
}
__device__ __forceinline__ uint32_t packh2(float a, float b) {
    __half2 h = __floats2half2_rn(a, b);
    return *(uint32_t*)&h;
}

// mma.sync m16n8k16 row.col f32.f16.f16.f32
__device__ __forceinline__ void mma16816(float d[4], const uint32_t a[4],
                                         uint32_t b0, uint32_t b1,
                                         const float c[4]) {
    asm volatile(
        "mma.sync.aligned.m16n8k16.row.col.f32.f16.f16.f32 "
        "{%0,%1,%2,%3}, {%4,%5,%6,%7}, {%8,%9}, {%10,%11,%12,%13};\n"
        : "=f"(d[0]), "=f"(d[1]), "=f"(d[2]), "=f"(d[3])
        : "r"(a[0]), "r"(a[1]), "r"(a[2]), "r"(a[3]),
          "r"(b0), "r"(b1),
          "f"(c[0]), "f"(c[1]), "f"(c[2]), "f"(c[3]));
}

// ---------------- GEMM (layer 0 only): C[M x 384] = A[M x 512]*W^T + b ----------------
// BM=BN=128, BK=16, 256 threads, 8x8 thread tile (1 B LDS per FMA).
__global__ __launch_bounds__(256) void gemm8_kernel(
    const float* __restrict__ A, const float* __restrict__ W,
    const float* __restrict__ bias, float* __restrict__ C,
    int M, int K)
{
    __shared__ __align__(16) float Ast[16][128];
    __shared__ __align__(16) float Bst[16][128];

    const int tid = threadIdx.x;
    const int m0 = blockIdx.y * 128;
    const int n0 = blockIdx.x * 128;
    const int lrow = tid >> 1;          // 0..127
    const int lk   = (tid & 1) * 8;     // 0 or 8
    const float* Ap = A + (size_t)(m0 + lrow) * K + lk;
    const float* Wp = W + (size_t)(n0 + lrow) * K + lk;
    const int tx = tid & 15;            // 0..15 (cols of 8)
    const int ty = tid >> 4;            // 0..15 (rows of 8)

    ull acc[8][4];
#pragma unroll
    for (int i = 0; i < 8; i++)
#pragma unroll
        for (int j = 0; j < 4; j++) acc[i][j] = pk2(0.f, 0.f);

    float4 av0 = *(const float4*)(Ap);
    float4 av1 = *(const float4*)(Ap + 4);
    float4 bv0 = *(const float4*)(Wp);
    float4 bv1 = *(const float4*)(Wp + 4);

    for (int kt = 0; kt < K; kt += 16) {
        __syncthreads();
        Ast[lk + 0][lrow] = av0.x; Ast[lk + 1][lrow] = av0.y;
        Ast[lk + 2][lrow] = av0.z; Ast[lk + 3][lrow] = av0.w;
        Ast[lk + 4][lrow] = av1.x; Ast[lk + 5][lrow] = av1.y;
        Ast[lk + 6][lrow] = av1.z; Ast[lk + 7][lrow] = av1.w;
        Bst[lk + 0][lrow] = bv0.x; Bst[lk + 1][lrow] = bv0.y;
        Bst[lk + 2][lrow] = bv0.z; Bst[lk + 3][lrow] = bv0.w;
        Bst[lk + 4][lrow] = bv1.x; Bst[lk + 5][lrow] = bv1.y;
        Bst[lk + 6][lrow] = bv1.z; Bst[lk + 7][lrow] = bv1.w;
        __syncthreads();
        if (kt + 16 < K) {
            av0 = *(const float4*)(Ap + kt + 16);
            av1 = *(const float4*)(Ap + kt + 20);
            bv0 = *(const float4*)(Wp + kt + 16);
            bv1 = *(const float4*)(Wp + kt + 20);
        }
#pragma unroll
        for (int k = 0; k < 16; k++) {
            float4 a0 = *(const float4*)&Ast[k][ty << 3];
            float4 a1 = *(const float4*)&Ast[k][(ty << 3) + 4];
            ulonglong2 bb0 = *(const ulonglong2*)&Bst[k][tx << 3];
            ulonglong2 bb1 = *(const ulonglong2*)&Bst[k][(tx << 3) + 4];
            float as[8] = {a0.x, a0.y, a0.z, a0.w, a1.x, a1.y, a1.z, a1.w};
#pragma unroll
            for (int i = 0; i < 8; i++) {
                ull pa = pk2(as[i], as[i]);
                acc[i][0] = ffma2(pa, bb0.x, acc[i][0]);
                acc[i][1] = ffma2(pa, bb0.y, acc[i][1]);
                acc[i][2] = ffma2(pa, bb1.x, acc[i][2]);
                acc[i][3] = ffma2(pa, bb1.y, acc[i][3]);
            }
        }
    }

    // epilogue
    float bs[8];
#pragma unroll
    for (int j = 0; j < 8; j++) bs[j] = bias[n0 + (tx << 3) + j];
#pragma unroll
    for (int i = 0; i < 8; i++) {
        const int m = m0 + (ty << 3) + i;
        float* Cp = C + (size_t)m * G3 + n0 + (tx << 3);
#pragma unroll
        for (int j = 0; j < 4; j++) {
            float c0, c1;
            upk2(acc[i][j], c0, c1);
            Cp[2 * j + 0] = c0 + bs[2 * j + 0];
            Cp[2 * j + 1] = c1 + bs[2 * j + 1];
        }
    }
}

// ================= layer-0 recurrence (R9 structure, publishes hi/lo y) =================
__global__ __launch_bounds__(256, 1) void gru_rec0(
    const float* __restrict__ w_hh,   // [384][128]
    const float* __restrict__ b_hh,   // [384]
    unsigned short* __restrict__ y_out) // [BATCH][SEQ][256] hi|lo
{
    __shared__ __align__(16) __half hbuf[2][2][HIDDEN];

    const int b = blockIdx.x;
    const int tid = threadIdx.x;
    const int wid = tid >> 5;
    const int lane = tid & 31;
    const int g  = lane >> 2;
    const int tg = lane & 3;
    const bool act = (tg == 0);
    const int u0 = wid * 16 + g;
    const int u1 = u0 + 8;

    uint32_t afr[3][8][4];
#pragma unroll
    for (int i = 0; i < 3; i++) {
        const int mbase = i * HIDDEN + wid * 16;
        const float* r0p = w_hh + (size_t)(mbase + g) * HIDDEN;
        const float* r1p = w_hh + (size_t)(mbase + 8 + g) * HIDDEN;
#pragma unroll
        for (int kt = 0; kt < 8; kt++) {
            const int c0 = kt * 16 + 2 * tg;
            float2 v00 = *(const float2*)(r0p + c0);
            float2 v10 = *(const float2*)(r1p + c0);
            float2 v01 = *(const float2*)(r0p + c0 + 8);
            float2 v11 = *(const float2*)(r1p + c0 + 8);
            afr[i][kt][0] = packh2(v00.x, v00.y);
            afr[i][kt][1] = packh2(v10.x, v10.y);
            afr[i][kt][2] = packh2(v01.x, v01.y);
            afr[i][kt][3] = packh2(v11.x, v11.y);
        }
    }

    float br0 = 0.f, bz0 = 0.f, bn0 = 0.f, br1 = 0.f, bz1 = 0.f, bn1 = 0.f;
    if (act) {
        br0 = b_hh[u0];            br1 = b_hh[u1];
        bz0 = b_hh[u0 + HIDDEN];   bz1 = b_hh[u1 + HIDDEN];
        bn0 = b_hh[u0 + 2*HIDDEN]; bn1 = b_hh[u1 + 2*HIDDEN];
    }

    ((uint32_t*)hbuf)[tid] = 0u;

    const float* gxb = g_gx + (size_t)b * SEQ * G3;
    unsigned short* yb = y_out + (size_t)b * SEQ * 256;

    float xr0 = 0.f, xz0 = 0.f, xn0 = 0.f, xr1 = 0.f, xz1 = 0.f, xn1 = 0.f;
    if (act) {
        xr0 = gxb[u0];            xr1 = gxb[u1];
        xz0 = gxb[u0 + HIDDEN];   xz1 = gxb[u1 + HIDDEN];
        xn0 = gxb[u0 + 2*HIDDEN]; xn1 = gxb[u1 + 2*HIDDEN];
    }
    float h0 = 0.f, h1 = 0.f;
    __syncthreads();

    for (int t = 0; t < SEQ; t++) {
        float nxr0 = 0.f, nxz0 = 0.f, nxn0 = 0.f, nxr1 = 0.f, nxz1 = 0.f, nxn1 = 0.f;
        if (act && t + 1 < SEQ) {
            const float* g1 = gxb + (size_t)(t + 1) * G3;
            nxr0 = __ldg(g1 + u0);            nxr1 = __ldg(g1 + u1);
            nxz0 = __ldg(g1 + u0 + HIDDEN);   nxz1 = __ldg(g1 + u1 + HIDDEN);
            nxn0 = __ldg(g1 + u0 + 2*HIDDEN); nxn1 = __ldg(g1 + u1 + 2*HIDDEN);
        }

        uint32_t bh0[8], bh1[8];
#pragma unroll
        for (int kt = 0; kt < 8; kt++) { bh0[kt] = 0u; bh1[kt] = 0u; }
        if (lane < 8) {
            const uint32_t* src = (const uint32_t*)hbuf[t & 1][lane >> 2];
#pragma unroll
            for (int kt = 0; kt < 8; kt++) {
                bh0[kt] = src[kt * 8 + tg];
                bh1[kt] = src[kt * 8 + 4 + tg];
            }
        }

        float gh[3][2];
#pragma unroll
        for (int i = 0; i < 3; i++) {
            float da[4] = {0.f, 0.f, 0.f, 0.f};
            float db[4] = {0.f, 0.f, 0.f, 0.f};
#pragma unroll
            for (int kt = 0; kt < 8; kt += 2) {
                mma16816(da, afr[i][kt],     bh0[kt],     bh1[kt],     da);
                mma16816(db, afr[i][kt + 1], bh0[kt + 1], bh1[kt + 1], db);
            }
            gh[i][0] = (da[0] + db[0]) + (da[1] + db[1]);
            gh[i][1] = (da[2] + db[2]) + (da[3] + db[3]);
        }

        if (act) {
            float r0g = sigm_fast(xr0 + gh[0][0] + br0);
            float r1g = sigm_fast(xr1 + gh[0][1] + br1);
            float z0g = sigm_fast(xz0 + gh[1][0] + bz0);
            float z1g = sigm_fast(xz1 + gh[1][1] + bz1);
            float n0g = tanh_fast(xn0 + r0g * (gh[2][0] + bn0));
            float n1g = tanh_fast(xn1 + r1g * (gh[2][1] + bn1));
            float hn0 = (1.0f - z0g) * n0g + z0g * h0;
            float hn1 = (1.0f - z1g) * n1g + z1g * h1;
            h0 = hn0; h1 = hn1;

            __half hi0 = __float2half_rn(hn0);
            __half hi1 = __float2half_rn(hn1);
            __half lo0 = __float2half_rn(hn0 - __half2float(hi0));
            __half lo1 = __float2half_rn(hn1 - __half2float(hi1));
            const int nb = (t + 1) & 1;
            hbuf[nb][0][u0] = hi0;  hbuf[nb][0][u1] = hi1;
            hbuf[nb][1][u0] = lo0;  hbuf[nb][1][u1] = lo1;

            unsigned short* yt = yb + (size_t)t * 256;
            yt[u0] = __half_as_ushort(hi0);
            yt[u1] = __half_as_ushort(hi1);
            yt[128 + u0] = __half_as_ushort(lo0);
            yt[128 + u1] = __half_as_ushort(lo1);
        }
        __syncthreads();

        xr0 = nxr0; xz0 = nxz0; xn0 = nxn0;
        xr1 = nxr1; xz1 = nxz1; xn1 = nxn1;
    }
}

// ================= fused recurrence (layers 1..4): W_ih folded into the step =================
// dyn smem: W_ih fragment spill, uint4 per ((wid*3+gate)*8+kt, lane) = 98304 B
#define WIH_SMEM 98304

__global__ __launch_bounds__(256, 1) void gru_recF(
    const float* __restrict__ w_hh,   // [384][128]
    const float* __restrict__ w_ih,   // [384][128]
    const float* __restrict__ b_ih,   // [384]
    const float* __restrict__ b_hh,   // [384]
    const unsigned short* __restrict__ y_in,  // [BATCH][SEQ][256] hi|lo
    unsigned short* __restrict__ y_out,       // or null (last layer)
    float* __restrict__ hfin)                 // or null
{
    extern __shared__ char dsm[];
    uint4* wih = (uint4*)dsm;
    __shared__ __align__(16) __half hbuf[2][2][HIDDEN];

    const int b = blockIdx.x;
    const int tid = threadIdx.x;
    const int wid = tid >> 5;
    const int lane = tid & 31;
    const int g  = lane >> 2;
    const int tg = lane & 3;
    const bool act = (tg == 0);
    const int u0 = wid * 16 + g;
    const int u1 = u0 + 8;

    // W_hh fragments in registers
    uint32_t afr[3][8][4];
#pragma unroll
    for (int i = 0; i < 3; i++) {
        const int mbase = i * HIDDEN + wid * 16;
        const float* r0p = w_hh + (size_t)(mbase + g) * HIDDEN;
        const float* r1p = w_hh + (size_t)(mbase + 8 + g) * HIDDEN;
#pragma unroll
        for (int kt = 0; kt < 8; kt++) {
            const int c0 = kt * 16 + 2 * tg;
            float2 v00 = *(const float2*)(r0p + c0);
            float2 v10 = *(const float2*)(r1p + c0);
            float2 v01 = *(const float2*)(r0p + c0 + 8);
            float2 v11 = *(const float2*)(r1p + c0 + 8);
            afr[i][kt][0] = packh2(v00.x, v00.y);
            afr[i][kt][1] = packh2(v10.x, v10.y);
            afr[i][kt][2] = packh2(v01.x, v01.y);
            afr[i][kt][3] = packh2(v11.x, v11.y);
        }
    }
    // W_ih fragments -> smem spill
#pragma unroll
    for (int i = 0; i < 3; i++) {
        const int mbase = i * HIDDEN + wid * 16;
        const float* r0p = w_ih + (size_t)(mbase + g) * HIDDEN;
        const float* r1p = w_ih + (size_t)(mbase + 8 + g) * HIDDEN;
#pragma unroll
        for (int kt = 0; kt < 8; kt++) {
            const int c0 = kt * 16 + 2 * tg;
            float2 v00 = *(const float2*)(r0p + c0);
            float2 v10 = *(const float2*)(r1p + c0);
            float2 v01 = *(const float2*)(r0p + c0 + 8);
            float2 v11 = *(const float2*)(r1p + c0 + 8);
            uint4 f;
            f.x = packh2(v00.x, v00.y);
            f.y = packh2(v10.x, v10.y);
            f.z = packh2(v01.x, v01.y);
            f.w = packh2(v11.x, v11.y);
            wih[((wid * 3 + i) * 8 + kt) * 32 + lane] = f;
        }
    }

    float br0 = 0.f, bz0 = 0.f, bin0 = 0.f, bhn0 = 0.f;
    float br1 = 0.f, bz1 = 0.f, bin1 = 0.f, bhn1 = 0.f;
    if (act) {
        br0 = b_ih[u0] + b_hh[u0];
        br1 = b_ih[u1] + b_hh[u1];
        bz0 = b_ih[u0 + HIDDEN] + b_hh[u0 + HIDDEN];
        bz1 = b_ih[u1 + HIDDEN] + b_hh[u1 + HIDDEN];
        bin0 = b_ih[u0 + 2*HIDDEN];  bin1 = b_ih[u1 + 2*HIDDEN];
        bhn0 = b_hh[u0 + 2*HIDDEN];  bhn1 = b_hh[u1 + 2*HIDDEN];
    }

    ((uint32_t*)hbuf)[tid] = 0u;

    const unsigned short* yib = y_in + (size_t)b * SEQ * 256;
    unsigned short* yob = y_out ? (y_out + (size_t)b * SEQ * 256) : (unsigned short*)0;

    // y fragments (lanes<8 carry cols 0/1 = hi/lo; others stay zero)
    uint32_t yc0[8], yc1[8];
#pragma unroll
    for (int kt = 0; kt < 8; kt++) { yc0[kt] = 0u; yc1[kt] = 0u; }
    if (lane < 8) {
        const uint32_t* src = (const uint32_t*)(yib + ((lane >= 4) ? 128 : 0));
#pragma unroll
        for (int kt = 0; kt < 8; kt++) {
            yc0[kt] = __ldg(src + kt * 8 + tg);
            yc1[kt] = __ldg(src + kt * 8 + 4 + tg);
        }
    }
    float h0 = 0.f, h1 = 0.f;
    __syncthreads();

    for (int t = 0; t < SEQ; t++) {
        // prefetch next y fragments
        uint32_t yn0[8], yn1[8];
#pragma unroll
        for (int kt = 0; kt < 8; kt++) { yn0[kt] = 0u; yn1[kt] = 0u; }
        if (lane < 8 && t + 1 < SEQ) {
            const uint32_t* src = (const uint32_t*)(yib + (size_t)(t + 1) * 256
                                                    + ((lane >= 4) ? 128 : 0));
#pragma unroll
            for (int kt = 0; kt < 8; kt++) {
                yn0[kt] = __ldg(src + kt * 8 + tg);
                yn1[kt] = __ldg(src + kt * 8 + 4 + tg);
            }
        }

        // h fragments from hbuf
        uint32_t bh0[8], bh1[8];
#pragma unroll
        for (int kt = 0; kt < 8; kt++) { bh0[kt] = 0u; bh1[kt] = 0u; }
        if (lane < 8) {
            const uint32_t* src = (const uint32_t*)hbuf[t & 1][lane >> 2];
#pragma unroll
            for (int kt = 0; kt < 8; kt++) {
                bh0[kt] = src[kt * 8 + tg];
                bh1[kt] = src[kt * 8 + 4 + tg];
            }
        }

        // per gate: h chain (da) + y chain (db) — independent, issue-overlapped
        float ghh[3][2], ghy[3][2];
#pragma unroll
        for (int i = 0; i < 3; i++) {
            float da[4] = {0.f, 0.f, 0.f, 0.f};
            float db[4] = {0.f, 0.f, 0.f, 0.f};
#pragma unroll
            for (int kt = 0; kt < 8; kt++) {
                mma16816(da, afr[i][kt], bh0[kt], bh1[kt], da);
                uint4 wf = wih[((wid * 3 + i) * 8 + kt) * 32 + lane];
                uint32_t aw[4] = {wf.x, wf.y, wf.z, wf.w};
                mma16816(db, aw, yc0[kt], yc1[kt], db);
            }
            ghh[i][0] = da[0] + da[1];  ghh[i][1] = da[2] + da[3];
            ghy[i][0] = db[0] + db[1];  ghy[i][1] = db[2] + db[3];
        }

        if (act) {
            float r0g = sigm_fast(ghy[0][0] + ghh[0][0] + br0);
            float r1g = sigm_fast(ghy[0][1] + ghh[0][1] + br1);
            float z0g = sigm_fast(ghy[1][0] + ghh[1][0] + bz0);
            float z1g = sigm_fast(ghy[1][1] + ghh[1][1] + bz1);
            float n0g = tanh_fast(ghy[2][0] + bin0 + r0g * (ghh[2][0] + bhn0));
            float n1g = tanh_fast(ghy[2][1] + bin1 + r1g * (ghh[2][1] + bhn1));
            float hn0 = (1.0f - z0g) * n0g + z0g * h0;
            float hn1 = (1.0f - z1g) * n1g + z1g * h1;
            h0 = hn0; h1 = hn1;

            __half hi0 = __float2half_rn(hn0);
            __half hi1 = __float2half_rn(hn1);
            __half lo0 = __float2half_rn(hn0 - __half2float(hi0));
            __half lo1 = __float2half_rn(hn1 - __half2float(hi1));
            const int nb = (t + 1) & 1;
            hbuf[nb][0][u0] = hi0;  hbuf[nb][0][u1] = hi1;
            hbuf[nb][1][u0] = lo0;  hbuf[nb][1][u1] = lo1;

            if (yob) {
                unsigned short* yt = yob + (size_t)t * 256;
                yt[u0] = __half_as_ushort(hi0);
                yt[u1] = __half_as_ushort(hi1);
                yt[128 + u0] = __half_as_ushort(lo0);
                yt[128 + u1] = __half_as_ushort(lo1);
            } else if (t == SEQ - 1) {
                g_hfinal[b][u0] = hn0;
                g_hfinal[b][u1] = hn1;
            }
        }
        __syncthreads();

#pragma unroll
        for (int kt = 0; kt < 8; kt++) { yc0[kt] = yn0[kt]; yc1[kt] = yn1[kt]; }
    }
    (void)hfin;
}

// ---------------- final FC ----------------
__global__ void fc_kernel(const float* __restrict__ hfinal,
                          const float* __restrict__ fc_w,
                          const float* __restrict__ fc_b,
                          float* __restrict__ out)
{
    const int b = blockIdx.x;
    const int o = threadIdx.x;   // 0..95
    const float* h = hfinal + (size_t)b * HIDDEN;
    const float* w = fc_w + (size_t)o * HIDDEN;
    float acc = fc_b[o];
#pragma unroll 16
    for (int k = 0; k < HIDDEN; k++) acc = fmaf(h[k], w[k], acc);
    out[b * OUTPUT_DIM + o] = acc;
}

// ---------------- host launch ----------------
extern "C" void kernel_launch(void* const* d_in, const int* in_sizes, int n_in,
                              void* d_out, int out_size)
{
    const float* x        = (const float*)d_in[0];
    const float* w_ih0    = (const float*)d_in[1];
    const float* w_ihrest = (const float*)d_in[2];
    const float* w_hh     = (const float*)d_in[3];
    const float* b_ih     = (const float*)d_in[4];
    const float* b_hh     = (const float*)d_in[5];
    const float* fc_w     = (const float*)d_in[6];
    const float* fc_b     = (const float*)d_in[7];
    float* out = (float*)d_out;

    float *gx, *hfin;
    unsigned short* y2h;
    cudaGetSymbolAddress((void**)&gx, g_gx);
    cudaGetSymbolAddress((void**)&hfin, g_hfinal);
    cudaGetSymbolAddress((void**)&y2h, g_y2h);

    cudaFuncSetAttribute(gru_recF, cudaFuncAttributeMaxDynamicSharedMemorySize, WIH_SMEM);

    const int M = BATCH * SEQ;
    dim3 ggrid(G3 / 128, M / 128);   // (3, 256)

    // layer 0: gx GEMM (K=512) + recurrence, publishes hi/lo y
    gemm8_kernel<<<ggrid, 256>>>(x, w_ih0, b_ih, gx, M, INPUT_DIM);
    gru_rec0<<<BATCH, 256>>>(w_hh, b_hh, y2h);

    // layers 1..4: fused W_ih + W_hh recurrence, ping-pong y buffers
    const size_t ybytes = (size_t)BATCH * SEQ * 256;   // ushorts per buffer
    for (int l = 1; l < NUM_LAYERS; l++) {
        unsigned short* src = y2h + ((l - 1) & 1) * ybytes;
        unsigned short* dst = y2h + (l & 1) * ybytes;
        gru_recF<<<BATCH, 256, WIH_SMEM>>>(
            w_hh + (size_t)l * G3 * HIDDEN,
            w_ihrest + (size_t)(l - 1) * G3 * HIDDEN,
            b_ih + (size_t)l * G3,
            b_hh + (size_t)l * G3,
            src,
            (l < NUM_LAYERS - 1) ? dst : (unsigned short*)0,
            (l == NUM_LAYERS - 1) ? hfin : (float*)0);
    }

    fc_kernel<<<BATCH, OUTPUT_DIM>>>(hfin, fc_w, fc_b, out);
}

// round 16
// speedup vs baseline: 1.9237x; 1.9237x over previous
#include <cuda_runtime.h>
#include <cuda_fp16.h>
#include <math.h>
#include <stdint.h>

#define BATCH 64
#define SEQ 512
#define INPUT_DIM 512
#define HIDDEN 128
#define G3 384            // 3*HIDDEN
#define NUM_LAYERS 5
#define OUTPUT_DIM 96
#define NGRP 16           // batch groups (4 batches each)
#define CHUNK 16          // wavefront sync granularity (steps)

typedef unsigned long long ull;

// ---------------- scratch (no allocs allowed) ----------------
__device__ float g_gx[BATCH * SEQ * G3];                          // layer-0 input gates
__device__ unsigned short g_y2h[NUM_LAYERS - 1][BATCH][SEQ][256]; // hi[128]|lo[128] fp16
__device__ int g_prog[NUM_LAYERS][NGRP];                          // per (layer, group) progress
__device__ float g_hfinal[BATCH][HIDDEN];                         // last layer, last timestep

// ---------------- helpers ----------------
__device__ __forceinline__ ull pk2(float a, float b) {
    ull r; asm("mov.b64 %0, {%1, %2};" : "=l"(r) : "f"(a), "f"(b)); return r;
}
__device__ __forceinline__ void upk2(ull v, float& a, float& b) {
    asm("mov.b64 {%0, %1}, %2;" : "=f"(a), "=f"(b) : "l"(v));
}
__device__ __forceinline__ ull ffma2(ull a, ull b, ull c) {
    ull d; asm("fma.rn.f32x2 %0, %1, %2, %3;" : "=l"(d) : "l"(a), "l"(b), "l"(c)); return d;
}
__device__ __forceinline__ float sigm_fast(float x) {
    float e = __expf(-x);
    return __fdividef(1.0f, 1.0f + e);
}
__device__ __forceinline__ float tanh_fast(float x) {
    float e = __expf(-2.0f * x);
    return 1.0f - __fdividef(2.0f * e, 1.0f + e);
}
__device__ __forceinline__ uint32_t packh2(float a, float b) {
    __half2 h = __floats2half2_rn(a, b);
    return *(uint32_t*)&h;
}
__device__ __forceinline__ int ld_acquire(const int* p) {
    int v;
    asm volatile("ld.acquire.gpu.global.b32 %0, [%1];" : "=r"(v) : "l"(p) : "memory");
    return v;
}
__device__ __forceinline__ void st_release(int* p, int v) {
    asm volatile("st.release.gpu.global.b32 [%0], %1;" :: "l"(p), "r"(v) : "memory");
}
__device__ __forceinline__ uint32_t ldcg_u32(const uint32_t* p) {
    uint32_t v;
    asm volatile("ld.global.cg.u32 %0, [%1];" : "=r"(v) : "l"(p));
    return v;
}

// mma.sync m16n8k16 row.col f32.f16.f16.f32
__device__ __forceinline__ void mma16816(float d[4], const uint32_t a[4],
                                         uint32_t b0, uint32_t b1,
                                         const float c[4]) {
    asm volatile(
        "mma.sync.aligned.m16n8k16.row.col.f32.f16.f16.f32 "
        "{%0,%1,%2,%3}, {%4,%5,%6,%7}, {%8,%9}, {%10,%11,%12,%13};\n"
        : "=f"(d[0]), "=f"(d[1]), "=f"(d[2]), "=f"(d[3])
        : "r"(a[0]), "r"(a[1]), "r"(a[2]), "r"(a[3]),
          "r"(b0), "r"(b1),
          "f"(c[0]), "f"(c[1]), "f"(c[2]), "f"(c[3]));
}

// ---------------- GEMM (layer 0 only): C[M x 384] = A[M x 512]*W^T + b ----------------
// BM=BN=128, BK=16, 256 threads, 8x8 thread tile.
__global__ __launch_bounds__(256) void gemm8_kernel(
    const float* __restrict__ A, const float* __restrict__ W,
    const float* __restrict__ bias, float* __restrict__ C,
    int M, int K)
{
    __shared__ __align__(16) float Ast[16][128];
    __shared__ __align__(16) float Bst[16][128];

    const int tid = threadIdx.x;
    const int m0 = blockIdx.y * 128;
    const int n0 = blockIdx.x * 128;
    const int lrow = tid >> 1;
    const int lk   = (tid & 1) * 8;
    const float* Ap = A + (size_t)(m0 + lrow) * K + lk;
    const float* Wp = W + (size_t)(n0 + lrow) * K + lk;
    const int tx = tid & 15;
    const int ty = tid >> 4;

    ull acc[8][4];
#pragma unroll
    for (int i = 0; i < 8; i++)
#pragma unroll
        for (int j = 0; j < 4; j++) acc[i][j] = pk2(0.f, 0.f);

    float4 av0 = *(const float4*)(Ap);
    float4 av1 = *(const float4*)(Ap + 4);
    float4 bv0 = *(const float4*)(Wp);
    float4 bv1 = *(const float4*)(Wp + 4);

    for (int kt = 0; kt < K; kt += 16) {
        __syncthreads();
        Ast[lk + 0][lrow] = av0.x; Ast[lk + 1][lrow] = av0.y;
        Ast[lk + 2][lrow] = av0.z; Ast[lk + 3][lrow] = av0.w;
        Ast[lk + 4][lrow] = av1.x; Ast[lk + 5][lrow] = av1.y;
        Ast[lk + 6][lrow] = av1.z; Ast[lk + 7][lrow] = av1.w;
        Bst[lk + 0][lrow] = bv0.x; Bst[lk + 1][lrow] = bv0.y;
        Bst[lk + 2][lrow] = bv0.z; Bst[lk + 3][lrow] = bv0.w;
        Bst[lk + 4][lrow] = bv1.x; Bst[lk + 5][lrow] = bv1.y;
        Bst[lk + 6][lrow] = bv1.z; Bst[lk + 7][lrow] = bv1.w;
        __syncthreads();
        if (kt + 16 < K) {
            av0 = *(const float4*)(Ap + kt + 16);
            av1 = *(const float4*)(Ap + kt + 20);
            bv0 = *(const float4*)(Wp + kt + 16);
            bv1 = *(const float4*)(Wp + kt + 20);
        }
#pragma unroll
        for (int k = 0; k < 16; k++) {
            float4 a0 = *(const float4*)&Ast[k][ty << 3];
            float4 a1 = *(const float4*)&Ast[k][(ty << 3) + 4];
            ulonglong2 bb0 = *(const ulonglong2*)&Bst[k][tx << 3];
            ulonglong2 bb1 = *(const ulonglong2*)&Bst[k][(tx << 3) + 4];
            float as[8] = {a0.x, a0.y, a0.z, a0.w, a1.x, a1.y, a1.z, a1.w};
#pragma unroll
            for (int i = 0; i < 8; i++) {
                ull pa = pk2(as[i], as[i]);
                acc[i][0] = ffma2(pa, bb0.x, acc[i][0]);
                acc[i][1] = ffma2(pa, bb0.y, acc[i][1]);
                acc[i][2] = ffma2(pa, bb1.x, acc[i][2]);
                acc[i][3] = ffma2(pa, bb1.y, acc[i][3]);
            }
        }
    }

    float bs[8];
#pragma unroll
    for (int j = 0; j < 8; j++) bs[j] = bias[n0 + (tx << 3) + j];
#pragma unroll
    for (int i = 0; i < 8; i++) {
        const int m = m0 + (ty << 3) + i;
        float* Cp = C + (size_t)m * G3 + n0 + (tx << 3);
#pragma unroll
        for (int j = 0; j < 4; j++) {
            float c0, c1;
            upk2(acc[i][j], c0, c1);
            Cp[2 * j + 0] = c0 + bs[2 * j + 0];
            Cp[2 * j + 1] = c1 + bs[2 * j + 1];
        }
    }
}

// ---------------- chunked wavefront GRU: all 5 layers concurrent ----------------
// grid = 80 CTAs: layer l = bx>>4, group grp = bx&15 (batches 4*grp..4*grp+3).
// 256 threads = 8 warps; warp w owns hidden units [16w,16w+16) (3 gate tiles).
// m16n8k16 B columns: col 2b = fp16_hi, col 2b+1 = fp16_lo of local batch b.
// Lane (g=lane>>2, tg=lane&3): batch tg, units u0=16w+g, u1=u0+8; gh = c0+c1.
// Layers>0 fuse W_ih (fragments spilled to smem); y via g_y2h hi/lo fp16.
// Cross-layer sync is CHUNKED: producer fences+releases prog every CHUNK
// steps; consumer refreshes a smem-cached prog only when it runs dry.
#define SMEM_WIH   0
#define SMEM_HBUF  98304
#define HB_STRIDE  68
#define SMEM_TOTAL (98304 + 2 * 8 * HB_STRIDE * 4)

__global__ void __launch_bounds__(256, 1) gru_wave(
    const float* __restrict__ w_hh_all,   // [5][384][128]
    const float* __restrict__ w_ihrest,   // [4][384][128]
    const float* __restrict__ b_ih_all,   // [5][384]
    const float* __restrict__ b_hh_all)   // [5][384]
{
    extern __shared__ char dsm[];
    uint4* wih = (uint4*)(dsm + SMEM_WIH);
    uint32_t* hball = (uint32_t*)(dsm + SMEM_HBUF);
    __shared__ int s_prog_sh;

    const int l   = blockIdx.x >> 4;
    const int grp = blockIdx.x & 15;
    const int tid = threadIdx.x;
    const int wid = tid >> 5;
    const int lane = tid & 31;
    const int g  = lane >> 2;
    const int tg = lane & 3;
    const int u0 = wid * 16 + g;
    const int u1 = u0 + 8;
    const int bat = 4 * grp + tg;          // this lane's batch (gate math)
    const int colc = lane >> 2;            // b-frag column 0..7
    const bool has_y = (l > 0);
    const bool has_cons = (l < NUM_LAYERS - 1);

    const float* w_hh = w_hh_all + (size_t)l * G3 * HIDDEN;
    const float* b_hh = b_hh_all + (size_t)l * G3;
    const float* b_ih = b_ih_all + (size_t)l * G3;

    // ---- W_hh fragments into registers ----
    uint32_t afr[3][8][4];
#pragma unroll
    for (int i = 0; i < 3; i++) {
        const int mbase = i * HIDDEN + wid * 16;
        const float* r0p = w_hh + (size_t)(mbase + g) * HIDDEN;
        const float* r1p = w_hh + (size_t)(mbase + 8 + g) * HIDDEN;
#pragma unroll
        for (int kt = 0; kt < 8; kt++) {
            const int c0 = kt * 16 + 2 * tg;
            float2 v00 = *(const float2*)(r0p + c0);
            float2 v10 = *(const float2*)(r1p + c0);
            float2 v01 = *(const float2*)(r0p + c0 + 8);
            float2 v11 = *(const float2*)(r1p + c0 + 8);
            afr[i][kt][0] = packh2(v00.x, v00.y);
            afr[i][kt][1] = packh2(v10.x, v10.y);
            afr[i][kt][2] = packh2(v01.x, v01.y);
            afr[i][kt][3] = packh2(v11.x, v11.y);
        }
    }

    // ---- W_ih fragments -> smem spill (layers > 0) ----
    if (has_y) {
        const float* wihp = w_ihrest + (size_t)(l - 1) * G3 * HIDDEN;
#pragma unroll
        for (int i = 0; i < 3; i++) {
            const int mbase = i * HIDDEN + wid * 16;
            const float* r0p = wihp + (size_t)(mbase + g) * HIDDEN;
            const float* r1p = wihp + (size_t)(mbase + 8 + g) * HIDDEN;
#pragma unroll
            for (int kt = 0; kt < 8; kt++) {
                const int c0 = kt * 16 + 2 * tg;
                float2 v00 = *(const float2*)(r0p + c0);
                float2 v10 = *(const float2*)(r1p + c0);
                float2 v01 = *(const float2*)(r0p + c0 + 8);
                float2 v11 = *(const float2*)(r1p + c0 + 8);
                uint4 f;
                f.x = packh2(v00.x, v00.y);
                f.y = packh2(v10.x, v10.y);
                f.z = packh2(v01.x, v01.y);
                f.w = packh2(v11.x, v11.y);
                wih[((wid * 3 + i) * 8 + kt) * 32 + lane] = f;
            }
        }
    }

    // ---- biases ----
    float br0, bz0, bin0, bhn0, br1, bz1, bin1, bhn1;
    if (has_y) {
        br0 = b_ih[u0] + b_hh[u0];               br1 = b_ih[u1] + b_hh[u1];
        bz0 = b_ih[u0 + HIDDEN] + b_hh[u0 + HIDDEN];
        bz1 = b_ih[u1 + HIDDEN] + b_hh[u1 + HIDDEN];
        bin0 = b_ih[u0 + 2 * HIDDEN];            bin1 = b_ih[u1 + 2 * HIDDEN];
    } else {
        br0 = b_hh[u0];                          br1 = b_hh[u1];
        bz0 = b_hh[u0 + HIDDEN];                 bz1 = b_hh[u1 + HIDDEN];
        bin0 = 0.f;                              bin1 = 0.f;
    }
    bhn0 = b_hh[u0 + 2 * HIDDEN];                bhn1 = b_hh[u1 + 2 * HIDDEN];

    // ---- zero hbuf (both buffers) ----
    for (int i = tid; i < 2 * 8 * HB_STRIDE; i += 256) hball[i] = 0u;

    // ---- input state ----
    const int ybatch = 4 * grp + (colc >> 1);   // batch whose vector this lane carries
    const int yhl = colc & 1;                   // 0 = hi stream, 1 = lo stream
    const float* gxb = g_gx + (size_t)bat * SEQ * G3;
    int* prog_prev = has_y ? &g_prog[l - 1][grp] : (int*)0;
    int prog_c = 0;

    float xr0 = 0.f, xz0 = 0.f, xn0 = 0.f, xr1 = 0.f, xz1 = 0.f, xn1 = 0.f;
    uint32_t yc0[8], yc1[8];
#pragma unroll
    for (int k = 0; k < 8; k++) { yc0[k] = 0u; yc1[k] = 0u; }

    if (!has_y) {
        xr0 = __ldg(gxb + u0);            xr1 = __ldg(gxb + u1);
        xz0 = __ldg(gxb + u0 + HIDDEN);   xz1 = __ldg(gxb + u1 + HIDDEN);
        xn0 = __ldg(gxb + u0 + 2*HIDDEN); xn1 = __ldg(gxb + u1 + 2*HIDDEN);
        __syncthreads();
    } else {
        // wait for y[0]
        if (tid == 0) {
            int v = ld_acquire(prog_prev);
            while (v < 1) { __nanosleep(128); v = ld_acquire(prog_prev); }
            s_prog_sh = v;
        }
        __syncthreads();
        prog_c = s_prog_sh;
        const uint32_t* src = (const uint32_t*)&g_y2h[l - 1][ybatch][0][yhl * 128];
#pragma unroll
        for (int k = 0; k < 8; k++) {
            yc0[k] = ldcg_u32(src + k * 8 + tg);
            yc1[k] = ldcg_u32(src + k * 8 + 4 + tg);
        }
    }
    float h0 = 0.f, h1 = 0.f;

    for (int t = 0; t < SEQ; t++) {
        // ---- chunked consumer wait: need y[t+1] => prog >= t+2 ----
        if (has_y && t + 1 < SEQ && prog_c < t + 2) {
            if (tid == 0) {
                int v = ld_acquire(prog_prev);
                while (v < t + 2) { __nanosleep(128); v = ld_acquire(prog_prev); }
                s_prog_sh = v;
            }
            __syncthreads();
            prog_c = s_prog_sh;
        }

        // ---- prefetch next step's input ----
        float nxr0 = 0.f, nxz0 = 0.f, nxn0 = 0.f, nxr1 = 0.f, nxz1 = 0.f, nxn1 = 0.f;
        uint32_t yn0[8], yn1[8];
#pragma unroll
        for (int k = 0; k < 8; k++) { yn0[k] = 0u; yn1[k] = 0u; }
        if (t + 1 < SEQ) {
            if (!has_y) {
                const float* g1 = gxb + (size_t)(t + 1) * G3;
                nxr0 = __ldg(g1 + u0);            nxr1 = __ldg(g1 + u1);
                nxz0 = __ldg(g1 + u0 + HIDDEN);   nxz1 = __ldg(g1 + u1 + HIDDEN);
                nxn0 = __ldg(g1 + u0 + 2*HIDDEN); nxn1 = __ldg(g1 + u1 + 2*HIDDEN);
            } else {
                const uint32_t* src = (const uint32_t*)&g_y2h[l - 1][ybatch][t + 1][yhl * 128];
#pragma unroll
                for (int k = 0; k < 8; k++) {
                    yn0[k] = ldcg_u32(src + k * 8 + tg);
                    yn1[k] = ldcg_u32(src + k * 8 + 4 + tg);
                }
            }
        }

        // ---- build h B-fragments from hbuf[t&1] ----
        const uint32_t* hb = hball + (t & 1) * 8 * HB_STRIDE + colc * HB_STRIDE;
        uint32_t bh0[8], bh1[8];
#pragma unroll
        for (int k = 0; k < 8; k++) {
            bh0[k] = hb[k * 8 + tg];
            bh1[k] = hb[k * 8 + 4 + tg];
        }

        // ---- mma: 3 gates; h chain + (layers>0) y chain ----
        float ghh[3][2], ghy[3][2];
#pragma unroll
        for (int i = 0; i < 3; i++) {
            float da[4] = {0.f, 0.f, 0.f, 0.f};
            float db[4] = {0.f, 0.f, 0.f, 0.f};
#pragma unroll
            for (int kt = 0; kt < 8; kt++)
                mma16816(da, afr[i][kt], bh0[kt], bh1[kt], da);
            if (has_y) {
#pragma unroll
                for (int kt = 0; kt < 8; kt++) {
                    uint4 wf = wih[((wid * 3 + i) * 8 + kt) * 32 + lane];
                    uint32_t aw[4] = {wf.x, wf.y, wf.z, wf.w};
                    mma16816(db, aw, yc0[kt], yc1[kt], db);
                }
            }
            ghh[i][0] = da[0] + da[1];  ghh[i][1] = da[2] + da[3];
            ghy[i][0] = db[0] + db[1];  ghy[i][1] = db[2] + db[3];
        }

        // ---- gates (all 32 lanes; batch tg, units u0/u1) ----
        float r0g = sigm_fast(xr0 + ghh[0][0] + ghy[0][0] + br0);
        float r1g = sigm_fast(xr1 + ghh[0][1] + ghy[0][1] + br1);
        float z0g = sigm_fast(xz0 + ghh[1][0] + ghy[1][0] + bz0);
        float z1g = sigm_fast(xz1 + ghh[1][1] + ghy[1][1] + bz1);
        float n0g = tanh_fast(xn0 + ghy[2][0] + bin0 + r0g * (ghh[2][0] + bhn0));
        float n1g = tanh_fast(xn1 + ghy[2][1] + bin1 + r1g * (ghh[2][1] + bhn1));
        float hn0 = (1.0f - z0g) * n0g + z0g * h0;
        float hn1 = (1.0f - z1g) * n1g + z1g * h1;
        h0 = hn0; h1 = hn1;

        __half hi0 = __float2half_rn(hn0);
        __half hi1 = __float2half_rn(hn1);
        __half lo0 = __float2half_rn(hn0 - __half2float(hi0));
        __half lo1 = __float2half_rn(hn1 - __half2float(hi1));

        // ---- store h into next hbuf (cols 2tg hi, 2tg+1 lo) ----
        __half* hbn = (__half*)(hball + ((t + 1) & 1) * 8 * HB_STRIDE);
        hbn[(2 * tg) * (2 * HB_STRIDE) + u0] = hi0;
        hbn[(2 * tg) * (2 * HB_STRIDE) + u1] = hi1;
        hbn[(2 * tg + 1) * (2 * HB_STRIDE) + u0] = lo0;
        hbn[(2 * tg + 1) * (2 * HB_STRIDE) + u1] = lo1;

        // ---- publish y to consumer layer (plain stores; fence only per chunk) ----
        if (has_cons) {
            unsigned short* yd = &g_y2h[l][bat][t][0];
            yd[u0] = __half_as_ushort(hi0);
            yd[u1] = __half_as_ushort(hi1);
            yd[128 + u0] = __half_as_ushort(lo0);
            yd[128 + u1] = __half_as_ushort(lo1);
        } else if (t == SEQ - 1) {
            g_hfinal[bat][u0] = hn0;
            g_hfinal[bat][u1] = hn1;
        }

        const bool pub = has_cons && (((t + 1) & (CHUNK - 1)) == 0);
        if (pub) __threadfence();
        __syncthreads();
        if (pub && tid == 0) st_release(&g_prog[l][grp], t + 1);

        // rotate prefetch buffers
        xr0 = nxr0; xz0 = nxz0; xn0 = nxn0;
        xr1 = nxr1; xz1 = nxz1; xn1 = nxn1;
#pragma unroll
        for (int k = 0; k < 8; k++) { yc0[k] = yn0[k]; yc1[k] = yn1[k]; }
    }
}

// ---------------- final FC ----------------
__global__ void fc_kernel(const float* __restrict__ hfinal,
                          const float* __restrict__ fc_w,
                          const float* __restrict__ fc_b,
                          float* __restrict__ out)
{
    const int b = blockIdx.x;
    const int o = threadIdx.x;   // 0..95
    const float* h = hfinal + (size_t)b * HIDDEN;
    const float* w = fc_w + (size_t)o * HIDDEN;
    float acc = fc_b[o];
#pragma unroll 16
    for (int k = 0; k < HIDDEN; k++) acc = fmaf(h[k], w[k], acc);
    out[b * OUTPUT_DIM + o] = acc;
}

// ---------------- host launch ----------------
extern "C" void kernel_launch(void* const* d_in, const int* in_sizes, int n_in,
                              void* d_out, int out_size)
{
    const float* x        = (const float*)d_in[0];
    const float* w_ih0    = (const float*)d_in[1];
    const float* w_ihrest = (const float*)d_in[2];
    const float* w_hh     = (const float*)d_in[3];
    const float* b_ih     = (const float*)d_in[4];
    const float* b_hh     = (const float*)d_in[5];
    const float* fc_w     = (const float*)d_in[6];
    const float* fc_b     = (const float*)d_in[7];
    float* out = (float*)d_out;

    float *gx, *hfin;
    int* prog;
    cudaGetSymbolAddress((void**)&gx, g_gx);
    cudaGetSymbolAddress((void**)&hfin, g_hfinal);
    cudaGetSymbolAddress((void**)&prog, g_prog);

    cudaFuncSetAttribute(gru_wave, cudaFuncAttributeMaxDynamicSharedMemorySize, SMEM_TOTAL);

    // reset progress counters (graph-capturable memset node)
    cudaMemsetAsync(prog, 0, sizeof(int) * NUM_LAYERS * NGRP);

    const int M = BATCH * SEQ;
    dim3 ggrid(G3 / 128, M / 128);   // (3, 256)
    gemm8_kernel<<<ggrid, 256>>>(x, w_ih0, b_ih, gx, M, INPUT_DIM);

    gru_wave<<<NUM_LAYERS * NGRP, 256, SMEM_TOTAL>>>(w_hh, w_ihrest, b_ih, b_hh);

    fc_kernel<<<BATCH, OUTPUT_DIM>>>(hfin, fc_w, fc_b, out);
}